// round 13
// baseline (speedup 1.0000x reference)
#include <cuda_runtime.h>
#include <cuda_bf16.h>
#include <math.h>
#include <stdint.h>

#define NN 160000
#define GG 800
#define NPG 200
#define EE 1280000
#define IN_F 31
#define HID 64
#define LD 64

// ---------------- static device scratch ----------------
__device__ int   g_deg[NN];
__device__ float g_norm[NN];
__device__ int2  g_row[NN];       // {start, end}
__device__ int   g_cursor[NN];
__device__ int   g_col[EE];
__device__ int   g_ctr;

// bf16 planes (GEMM inputs / pool input), element-addressed [N][64]
__device__ uint16_t g_M0[NN * LD];
__device__ uint16_t g_P0[NN * LD];
__device__ uint16_t g_P1[NN * LD];
__device__ uint16_t g_T1[NN * LD];
__device__ uint16_t g_T2[NN * LD];
// norm-scaled gather planes, bf16x2-packed words [N][32]
__device__ uint32_t g_M0s[NN * 32];
__device__ uint32_t g_P0s[NN * 32];
__device__ uint32_t g_P1s[NN * 32];
__device__ uint32_t g_T1s[NN * 32];

// weights bf16 hi/lo, pair-interleaved: word idx = (((l*64+n)*6+c)*8+P)*2+half
__device__ uint32_t g_Wbh[4 * 64 * 96];
__device__ uint32_t g_Wbl[4 * 64 * 96];

__device__ __forceinline__ uint32_t pack_bf16x2(float x, float y) {
    uint32_t r;
    asm("cvt.rn.bf16x2.f32 %0, %1, %2;" : "=r"(r) : "f"(y), "f"(x));
    return r;
}
__device__ __forceinline__ float blo(uint32_t w) { return __uint_as_float(w << 16); }
__device__ __forceinline__ float bhi(uint32_t w) { return __uint_as_float(w & 0xffff0000u); }
__device__ __forceinline__ float b2f(uint16_t h) { return __uint_as_float(((uint32_t)h) << 16); }

// ---------------- launch 0: degree count + weight prep + ctr reset ----------------
#define DEG_NB 5000
#define WPREP_NB 96

__global__ void k_fused(const int* __restrict__ dst,
                        const float* __restrict__ W0, const float* __restrict__ W1,
                        const float* __restrict__ W2, const float* __restrict__ W3) {
    int b = blockIdx.x, t = threadIdx.x;
    if (b == 0 && t == 0) g_ctr = 0;
    if (b < DEG_NB) {
        int i = b * 256 + t;
        if (i < EE) atomicAdd(&g_deg[dst[i]], 1);
    } else {
        int idx = (b - DEG_NB) * 256 + t;  // < 4*64*96
        int l = idx / 6144;
        int rem = idx - l * 6144;
        int n = rem / 96;
        int g = rem - n * 96;
        int c = g >> 4, local = g & 15;
        int ks = local >> 3, lmod = local & 7;
        int half = lmod >> 2, lm = lmod & 3;
        int P = ks * 4 + lm;
        int word = (((l * 64 + n) * 6 + c) * 8 + P) * 2 + half;
        float v[2];
#pragma unroll
        for (int u = 0; u < 2; u++) {
            int k = g * 2 + u;
            if (l == 0) {
                int hop = k >> 6, cc = k & 63;
                v[u] = (cc < IN_F) ? W0[(hop * IN_F + cc) * 64 + n] : 0.0f;
            } else if (l == 1) v[u] = W1[k * 64 + n];
            else if (l == 2)   v[u] = W2[k * 64 + n];
            else               v[u] = W3[k * 64 + n];
        }
        uint32_t hw = pack_bf16x2(v[0], v[1]);
        uint32_t lw = pack_bf16x2(v[0] - blo(hw), v[1] - bhi(hw));
        g_Wbh[word] = hw;
        g_Wbl[word] = lw;
    }
}

// ---------------- launch 1: per-node segment base via warp-agg atomic ----------------
__global__ void k_base() {
    int i = blockIdx.x * blockDim.x + threadIdx.x;
    int lane = threadIdx.x & 31;
    int d = (i < NN) ? g_deg[i] : 0;
    int sc = d;
#pragma unroll
    for (int off = 1; off < 32; off <<= 1) {
        int t = __shfl_up_sync(0xffffffffu, sc, off);
        if (lane >= off) sc += t;
    }
    int total = __shfl_sync(0xffffffffu, sc, 31);
    int base = 0;
    if (lane == 31 && total > 0) base = atomicAdd(&g_ctr, total);
    base = __shfl_sync(0xffffffffu, base, 31);
    if (i < NN) {
        int start = base + sc - d;
        g_row[i] = make_int2(start, start + d);
        g_cursor[i] = start;
        g_norm[i] = rsqrtf(fmaxf((float)d, 1.0f));
        g_deg[i] = 0;   // ready for next replay
    }
}

// ---------------- launch 2: edge fill + x pad/pack ----------------
#define FILL_NB 5000
#define PAD_NB 20000   // NN*32 words / 256

__global__ void k_fillpad(const int* __restrict__ src, const int* __restrict__ dst,
                          const float* __restrict__ x) {
    int b = blockIdx.x, t = threadIdx.x;
    if (b < FILL_NB) {
        int i = b * 256 + t;
        if (i < EE) {
            int p = atomicAdd(&g_cursor[dst[i]], 1);
            g_col[p] = src[i];
        }
    } else {
        int idx = (b - FILL_NB) * 256 + t;   // < NN*32 words
        int node = idx >> 5, wp = idx & 31;
        int c0 = wp * 2, c1 = wp * 2 + 1;
        float v0 = (c0 < IN_F) ? x[node * IN_F + c0] : 0.0f;
        float v1 = (c1 < IN_F) ? x[node * IN_F + c1] : 0.0f;
        ((uint32_t*)g_M0)[idx] = pack_bf16x2(v0, v1);
        float nv = g_norm[node];
        g_M0s[idx] = pack_bf16x2(v0 * nv, v1 * nv);
    }
}

// ---------------- SpMM hop: 8-lane group per 4 nodes (serial), bf16x2 planes ----
// Gin pre-scaled bf16x2 words. out = norm[v]*sum -> bf16 Hout; if WS also write
// norm[v]*out as bf16x2 words. NV=1: lower 32 cols; NV=2: 64 cols.
// 4 consecutive nodes per lane-group: warp time ~ max of SUMS of 4 degrees,
// not max of single degrees -> much lower imbalance inflation.
template <int NV, bool WS>
__global__ void __launch_bounds__(256) k_spmm(const uint32_t* __restrict__ Gin,
                                              uint16_t* __restrict__ Hout,
                                              uint32_t* __restrict__ Hsout) {
    int tid = threadIdx.x;
    int q = tid & 7;
    int node0 = blockIdx.x * 128 + (tid >> 3) * 4;   // grid 1250 * 128 = NN
    const uint32_t* gbase = Gin + q * (2 * NV);

#pragma unroll
    for (int nn = 0; nn < 4; nn++) {
        int node = node0 + nn;
        int2 se = g_row[node];

        float a0 = 0.f, a1 = 0.f, a2 = 0.f, a3 = 0.f;
        float a4 = 0.f, a5 = 0.f, a6 = 0.f, a7 = 0.f;

        int j = se.x;
        for (; j + 1 < se.y; j += 2) {
            int u0 = __ldg(&g_col[j]);
            int u1 = __ldg(&g_col[j + 1]);
            if (NV == 1) {
                uint2 p0 = *(const uint2*)(gbase + (size_t)u0 * 32);
                uint2 p1 = *(const uint2*)(gbase + (size_t)u1 * 32);
                a0 += blo(p0.x) + blo(p1.x); a1 += bhi(p0.x) + bhi(p1.x);
                a2 += blo(p0.y) + blo(p1.y); a3 += bhi(p0.y) + bhi(p1.y);
            } else {
                uint4 p0 = *(const uint4*)(gbase + (size_t)u0 * 32);
                uint4 p1 = *(const uint4*)(gbase + (size_t)u1 * 32);
                a0 += blo(p0.x) + blo(p1.x); a1 += bhi(p0.x) + bhi(p1.x);
                a2 += blo(p0.y) + blo(p1.y); a3 += bhi(p0.y) + bhi(p1.y);
                a4 += blo(p0.z) + blo(p1.z); a5 += bhi(p0.z) + bhi(p1.z);
                a6 += blo(p0.w) + blo(p1.w); a7 += bhi(p0.w) + bhi(p1.w);
            }
        }
        if (j < se.y) {
            int u = __ldg(&g_col[j]);
            if (NV == 1) {
                uint2 p = *(const uint2*)(gbase + (size_t)u * 32);
                a0 += blo(p.x); a1 += bhi(p.x);
                a2 += blo(p.y); a3 += bhi(p.y);
            } else {
                uint4 p = *(const uint4*)(gbase + (size_t)u * 32);
                a0 += blo(p.x); a1 += bhi(p.x);
                a2 += blo(p.y); a3 += bhi(p.y);
                a4 += blo(p.z); a5 += bhi(p.z);
                a6 += blo(p.w); a7 += bhi(p.w);
            }
        }

        float nv = g_norm[node];
        float o0 = nv * a0, o1 = nv * a1, o2 = nv * a2, o3 = nv * a3;
        if (NV == 1) {
            size_t eb = (size_t)node * 64 + q * 4;
            *(uint2*)&Hout[eb] = make_uint2(pack_bf16x2(o0, o1), pack_bf16x2(o2, o3));
            if (WS) {
                size_t wb = (size_t)node * 32 + q * 2;
                *(uint2*)&Hsout[wb] =
                    make_uint2(pack_bf16x2(nv * o0, nv * o1), pack_bf16x2(nv * o2, nv * o3));
            }
        } else {
            float o4 = nv * a4, o5 = nv * a5, o6 = nv * a6, o7 = nv * a7;
            size_t eb = (size_t)node * 64 + q * 8;
            uint4 w;
            w.x = pack_bf16x2(o0, o1); w.y = pack_bf16x2(o2, o3);
            w.z = pack_bf16x2(o4, o5); w.w = pack_bf16x2(o6, o7);
            *(uint4*)&Hout[eb] = w;
            if (WS) {
                size_t wb = (size_t)node * 32 + q * 4;
                uint4 ws;
                ws.x = pack_bf16x2(nv * o0, nv * o1); ws.y = pack_bf16x2(nv * o2, nv * o3);
                ws.z = pack_bf16x2(nv * o4, nv * o5); ws.w = pack_bf16x2(nv * o6, nv * o7);
                *(uint4*)&Hsout[wb] = ws;
            }
        }
    }
}

// ---------------- bf16 tensor-core GEMM + bias + ReLU ----------------
#define ASTR 20
#define BPSTR 12

__device__ __forceinline__ void mma_bf16(float* c, uint32_t a0, uint32_t a1,
                                         uint32_t a2, uint32_t a3,
                                         uint32_t b0, uint32_t b1) {
    asm volatile(
        "mma.sync.aligned.m16n8k16.row.col.f32.bf16.bf16.f32 "
        "{%0,%1,%2,%3}, {%4,%5,%6,%7}, {%8,%9}, {%0,%1,%2,%3};"
        : "+f"(c[0]), "+f"(c[1]), "+f"(c[2]), "+f"(c[3])
        : "r"(a0), "r"(a1), "r"(a2), "r"(a3), "r"(b0), "r"(b1));
}

template <bool WSC>
__global__ void __launch_bounds__(256) k_gemm_tc(
    const uint16_t* __restrict__ H0, const uint16_t* __restrict__ H1,
    const uint16_t* __restrict__ H2, const uint32_t* __restrict__ Wbh,
    const uint32_t* __restrict__ Wbl, const float* __restrict__ bias,
    uint16_t* __restrict__ Out, uint32_t* __restrict__ OutS)
{
    __shared__ float sbias[64];
    __shared__ uint32_t As[128 * ASTR];
    __shared__ uint2 Bhi2[64 * BPSTR];
    __shared__ uint2 Blo2[64 * BPSTR];

    int tid = threadIdx.x;
    int warp = tid >> 5, lane = tid & 31;
    int lg = lane >> 2, lm = lane & 3;
    int row0 = blockIdx.x * 128;
    if (tid < 64) sbias[tid] = bias[tid];

    float acc[8][4];
#pragma unroll
    for (int nt = 0; nt < 8; nt++)
#pragma unroll
        for (int jj = 0; jj < 4; jj++) acc[nt][jj] = 0.f;

    const uint16_t* bufs[3] = {H0, H1, H2};
    const uint2* Wh2 = (const uint2*)Wbh;
    const uint2* Wl2 = (const uint2*)Wbl;

    for (int c = 0; c < 6; c++) {
        __syncthreads();
        {
            const uint16_t* H = bufs[c >> 1];
            int half = (c & 1) * 32;
#pragma unroll
            for (int it = 0; it < 2; it++) {
                int idx = tid + it * 256;
                int r = idx >> 2, q = idx & 3;
                uint4 w = *(const uint4*)&H[(size_t)(row0 + r) * 64 + half + q * 8];
                *(uint4*)&As[r * ASTR + q * 4] = w;
            }
        }
        {
#pragma unroll
            for (int it = 0; it < 2; it++) {
                int idx = tid + it * 256;
                int n = idx >> 3, P = idx & 7;
                int srcp = (n * 6 + c) * 8 + P;
                Bhi2[n * BPSTR + P] = Wh2[srcp];
                Blo2[n * BPSTR + P] = Wl2[srcp];
            }
        }
        __syncthreads();

        int rA = warp * 16 + lg;
#pragma unroll
        for (int ks = 0; ks < 2; ks++) {
            int kb = ks * 8 + lm;
            uint32_t a0 = As[rA * ASTR + kb];
            uint32_t a1 = As[(rA + 8) * ASTR + kb];
            uint32_t a2 = As[rA * ASTR + kb + 4];
            uint32_t a3 = As[(rA + 8) * ASTR + kb + 4];
            int bp = ks * 4 + lm;
#pragma unroll
            for (int nt = 0; nt < 8; nt++) {
                int col = nt * 8 + lg;
                uint2 bh = Bhi2[col * BPSTR + bp];
                uint2 bl = Blo2[col * BPSTR + bp];
                mma_bf16(acc[nt], a0, a1, a2, a3, bh.x, bh.y);
                mma_bf16(acc[nt], a0, a1, a2, a3, bl.x, bl.y);
            }
        }
    }

    int r = row0 + warp * 16 + lg;
    float nv0 = 1.f, nv1 = 1.f;
    if (WSC) { nv0 = g_norm[r]; nv1 = g_norm[r + 8]; }
    int cb = lm * 2;
#pragma unroll
    for (int nt = 0; nt < 8; nt++) {
        int col = nt * 8 + cb;
        float b0 = sbias[col], b1 = sbias[col + 1];
        float v00 = fmaxf(acc[nt][0] + b0, 0.f);
        float v01 = fmaxf(acc[nt][1] + b1, 0.f);
        float v10 = fmaxf(acc[nt][2] + b0, 0.f);
        float v11 = fmaxf(acc[nt][3] + b1, 0.f);
        *(uint32_t*)&Out[(size_t)r * 64 + col] = pack_bf16x2(v00, v01);
        *(uint32_t*)&Out[(size_t)(r + 8) * 64 + col] = pack_bf16x2(v10, v11);
        if (WSC) {
            OutS[(size_t)r * 32 + (col >> 1)] = pack_bf16x2(nv0 * v00, nv0 * v01);
            OutS[(size_t)(r + 8) * 32 + (col >> 1)] = pack_bf16x2(nv1 * v10, nv1 * v11);
        }
    }
}

// ---------------- per-graph attention pooling (bf16 plane input) ----------------
__global__ void k_pool(const uint16_t* __restrict__ H, const float* __restrict__ Wg,
                       const float* __restrict__ bg, float* __restrict__ out) {
    int g = blockIdx.x;
    __shared__ float sWg[64];
    __shared__ float sgate[NPG];
    __shared__ float red[256];
    int t = threadIdx.x;
    if (t < 64) sWg[t] = Wg[t];
    __syncthreads();

    int lane = t & 31, w = t >> 5;
    float bgv = bg[0];
    for (int n = w; n < NPG; n += 8) {
        const uint16_t* hp = H + (size_t)(g * NPG + n) * LD;
        float v = b2f(hp[lane]) * sWg[lane] + b2f(hp[lane + 32]) * sWg[lane + 32];
#pragma unroll
        for (int o = 16; o; o >>= 1) v += __shfl_xor_sync(0xffffffffu, v, o);
        if (lane == 0) sgate[n] = v + bgv;
    }
    __syncthreads();

    float m = -INFINITY;
    for (int n = t; n < NPG; n += 256) m = fmaxf(m, sgate[n]);
    red[t] = m;
    __syncthreads();
    for (int s = 128; s; s >>= 1) { if (t < s) red[t] = fmaxf(red[t], red[t + s]); __syncthreads(); }
    float gmax = red[0];
    __syncthreads();

    float ssum = 0.f;
    for (int n = t; n < NPG; n += 256) {
        float e = expf(sgate[n] - gmax);
        sgate[n] = e;
        ssum += e;
    }
    red[t] = ssum;
    __syncthreads();
    for (int s = 128; s; s >>= 1) { if (t < s) red[t] += red[t + s]; __syncthreads(); }
    float z = red[0];
    __syncthreads();

    int d = t & 63, p = t >> 6;
    float acc = 0.f;
    for (int n = p; n < NPG; n += 4)
        acc += sgate[n] * b2f(H[(size_t)(g * NPG + n) * LD + d]);
    red[t] = acc;
    __syncthreads();
    if (t < 64)
        out[g * 64 + t] = (red[t] + red[t + 64] + red[t + 128] + red[t + 192]) / z;
}

// ---------------- launch ----------------
extern "C" void kernel_launch(void* const* d_in, const int* in_sizes, int n_in,
                              void* d_out, int out_size) {
    const float* x   = (const float*)d_in[0];
    const int*   src = (const int*)d_in[1];
    const int*   dst = (const int*)d_in[2];
    const float* W0 = (const float*)d_in[4];
    const float* b0 = (const float*)d_in[5];
    const float* W1 = (const float*)d_in[6];
    const float* b1 = (const float*)d_in[7];
    const float* W2 = (const float*)d_in[8];
    const float* b2 = (const float*)d_in[9];
    const float* W3 = (const float*)d_in[10];
    const float* b3 = (const float*)d_in[11];
    const float* Wg = (const float*)d_in[12];
    const float* bg = (const float*)d_in[13];
    float* out = (float*)d_out;

    uint16_t *M0, *P0, *P1, *T1, *T2;
    uint32_t *M0s, *P0s, *P1s, *T1s, *Wbh, *Wbl;
    cudaGetSymbolAddress((void**)&M0, g_M0);
    cudaGetSymbolAddress((void**)&P0, g_P0);
    cudaGetSymbolAddress((void**)&P1, g_P1);
    cudaGetSymbolAddress((void**)&T1, g_T1);
    cudaGetSymbolAddress((void**)&T2, g_T2);
    cudaGetSymbolAddress((void**)&M0s, g_M0s);
    cudaGetSymbolAddress((void**)&P0s, g_P0s);
    cudaGetSymbolAddress((void**)&P1s, g_P1s);
    cudaGetSymbolAddress((void**)&T1s, g_T1s);
    cudaGetSymbolAddress((void**)&Wbh, g_Wbh);
    cudaGetSymbolAddress((void**)&Wbl, g_Wbl);

    k_fused<<<DEG_NB + WPREP_NB, 256>>>(dst, W0, W1, W2, W3);        // #0
    k_base<<<(NN + 255) / 256, 256>>>();                             // #1
    k_fillpad<<<FILL_NB + PAD_NB, 256>>>(src, dst, x);               // #2

    const int sgrid = NN / 128;   // 1250 (4 nodes per 8-lane group)
    const int ggrid = NN / 128;   // 1250

    // ---- layer 0 ----  (#3 = first spmm — ncu target)
    k_spmm<1, true><<<sgrid, 256>>>(M0s, T1, T1s);
    k_spmm<1, false><<<sgrid, 256>>>(T1s, T2, nullptr);
    k_gemm_tc<true><<<ggrid, 256>>>(M0, T1, T2, Wbh + 0 * 6144, Wbl + 0 * 6144, b0, P0, P0s);

    // ---- layer 1 ----
    k_spmm<2, true><<<sgrid, 256>>>(P0s, T1, T1s);
    k_spmm<2, false><<<sgrid, 256>>>(T1s, T2, nullptr);
    k_gemm_tc<true><<<ggrid, 256>>>(P0, T1, T2, Wbh + 1 * 6144, Wbl + 1 * 6144, b1, P1, P1s);

    // ---- layer 2 ----
    k_spmm<2, true><<<sgrid, 256>>>(P1s, T1, T1s);
    k_spmm<2, false><<<sgrid, 256>>>(T1s, T2, nullptr);
    k_gemm_tc<true><<<ggrid, 256>>>(P1, T1, T2, Wbh + 2 * 6144, Wbl + 2 * 6144, b2, P0, P0s);

    // ---- layer 3 ----
    k_spmm<2, true><<<sgrid, 256>>>(P0s, T1, T1s);
    k_spmm<2, false><<<sgrid, 256>>>(T1s, T2, nullptr);
    k_gemm_tc<false><<<ggrid, 256>>>(P0, T1, T2, Wbh + 3 * 6144, Wbl + 3 * 6144, b3, P1, nullptr);

    // ---- pooling ----
    k_pool<<<GG, 256>>>(P1, Wg, bg, out);
}

// round 16
// speedup vs baseline: 1.1014x; 1.1014x over previous
#include <cuda_runtime.h>
#include <cuda_bf16.h>
#include <math.h>
#include <stdint.h>

#define NN 160000
#define GG 800
#define NPG 200
#define EE 1280000
#define IN_F 31
#define HID 64
#define LD 64

// ---------------- static device scratch ----------------
__device__ int   g_deg[NN];
__device__ float g_norm[NN];
__device__ int2  g_row[NN];       // {start, end}
__device__ int   g_cursor[NN];
__device__ int   g_col[EE];
__device__ int   g_ctr;

// bf16 planes (GEMM inputs / pool input), element-addressed [N][64]
__device__ uint16_t g_M0[NN * LD];
__device__ uint16_t g_P0[NN * LD];
__device__ uint16_t g_P1[NN * LD];
__device__ uint16_t g_T1[NN * LD];
__device__ uint16_t g_T2[NN * LD];
// norm-scaled gather planes, bf16x2-packed words [N][32]
__device__ uint32_t g_M0s[NN * 32];
__device__ uint32_t g_P0s[NN * 32];
__device__ uint32_t g_P1s[NN * 32];
__device__ uint32_t g_T1s[NN * 32];

// weights bf16 hi/lo in QUADS: quad idx = ((l*64+n)*6+c)*8+P,
// quad = {hi_half0, hi_half1, lo_half0, lo_half1}; 12288 words per layer
__device__ uint32_t g_Wq[4 * 64 * 96 * 2];   // 12288 quads * 4 words total

__device__ __forceinline__ uint32_t pack_bf16x2(float x, float y) {
    uint32_t r;
    asm("cvt.rn.bf16x2.f32 %0, %1, %2;" : "=r"(r) : "f"(y), "f"(x));
    return r;
}
__device__ __forceinline__ float blo(uint32_t w) { return __uint_as_float(w << 16); }
__device__ __forceinline__ float bhi(uint32_t w) { return __uint_as_float(w & 0xffff0000u); }
__device__ __forceinline__ float b2f(uint16_t h) { return __uint_as_float(((uint32_t)h) << 16); }

// ---------------- launch 0: degree count + weight prep + ctr reset ----------------
#define DEG_NB 5000
#define WPREP_NB 96

__global__ void k_fused(const int* __restrict__ dst,
                        const float* __restrict__ W0, const float* __restrict__ W1,
                        const float* __restrict__ W2, const float* __restrict__ W3) {
    int b = blockIdx.x, t = threadIdx.x;
    if (b == 0 && t == 0) g_ctr = 0;
    if (b < DEG_NB) {
        int i = b * 256 + t;
        if (i < EE) atomicAdd(&g_deg[dst[i]], 1);
    } else {
        int idx = (b - DEG_NB) * 256 + t;  // < 4*64*96
        int l = idx / 6144;
        int rem = idx - l * 6144;
        int n = rem / 96;
        int g = rem - n * 96;
        int c = g >> 4, local = g & 15;
        int ks = local >> 3, lmod = local & 7;
        int half = lmod >> 2, lm = lmod & 3;
        int P = ks * 4 + lm;
        int quad = ((l * 64 + n) * 6 + c) * 8 + P;
        float v[2];
#pragma unroll
        for (int u = 0; u < 2; u++) {
            int k = g * 2 + u;
            if (l == 0) {
                int hop = k >> 6, cc = k & 63;
                v[u] = (cc < IN_F) ? W0[(hop * IN_F + cc) * 64 + n] : 0.0f;
            } else if (l == 1) v[u] = W1[k * 64 + n];
            else if (l == 2)   v[u] = W2[k * 64 + n];
            else               v[u] = W3[k * 64 + n];
        }
        uint32_t hw = pack_bf16x2(v[0], v[1]);
        uint32_t lw = pack_bf16x2(v[0] - blo(hw), v[1] - bhi(hw));
        g_Wq[quad * 4 + half] = hw;
        g_Wq[quad * 4 + 2 + half] = lw;
    }
}

// ---------------- launch 1: per-node segment base via warp-agg atomic ----------------
__global__ void k_base() {
    int i = blockIdx.x * blockDim.x + threadIdx.x;
    int lane = threadIdx.x & 31;
    int d = (i < NN) ? g_deg[i] : 0;
    int sc = d;
#pragma unroll
    for (int off = 1; off < 32; off <<= 1) {
        int t = __shfl_up_sync(0xffffffffu, sc, off);
        if (lane >= off) sc += t;
    }
    int total = __shfl_sync(0xffffffffu, sc, 31);
    int base = 0;
    if (lane == 31 && total > 0) base = atomicAdd(&g_ctr, total);
    base = __shfl_sync(0xffffffffu, base, 31);
    if (i < NN) {
        int start = base + sc - d;
        g_row[i] = make_int2(start, start + d);
        g_cursor[i] = start;
        g_norm[i] = rsqrtf(fmaxf((float)d, 1.0f));
        g_deg[i] = 0;   // ready for next replay
    }
}

// ---------------- launch 2: edge fill + x pad/pack ----------------
#define FILL_NB 5000
#define PAD_NB 20000   // NN*32 words / 256

__global__ void k_fillpad(const int* __restrict__ src, const int* __restrict__ dst,
                          const float* __restrict__ x) {
    int b = blockIdx.x, t = threadIdx.x;
    if (b < FILL_NB) {
        int i = b * 256 + t;
        if (i < EE) {
            int p = atomicAdd(&g_cursor[dst[i]], 1);
            g_col[p] = src[i];
        }
    } else {
        int idx = (b - FILL_NB) * 256 + t;   // < NN*32 words
        int node = idx >> 5, wp = idx & 31;
        int c0 = wp * 2, c1 = wp * 2 + 1;
        float v0 = (c0 < IN_F) ? x[node * IN_F + c0] : 0.0f;
        float v1 = (c1 < IN_F) ? x[node * IN_F + c1] : 0.0f;
        ((uint32_t*)g_M0)[idx] = pack_bf16x2(v0, v1);
        float nv = g_norm[node];
        g_M0s[idx] = pack_bf16x2(v0 * nv, v1 * nv);
    }
}

// ---------------- SpMM hop: 8-lane group per node, bf16x2 gather planes ---------
// (exact R9 structure — proven best)
template <int NV, bool WS>
__global__ void __launch_bounds__(256) k_spmm(const uint32_t* __restrict__ Gin,
                                              uint16_t* __restrict__ Hout,
                                              uint32_t* __restrict__ Hsout) {
    int tid = threadIdx.x;
    int node = blockIdx.x * 32 + (tid >> 3);   // grid 5000 * 32 = NN exactly
    int q = tid & 7;
    int2 se = g_row[node];
    const uint32_t* gbase = Gin + q * (2 * NV);

    float a0 = 0.f, a1 = 0.f, a2 = 0.f, a3 = 0.f;
    float a4 = 0.f, a5 = 0.f, a6 = 0.f, a7 = 0.f;

    int j = se.x;
    for (; j + 1 < se.y; j += 2) {
        int u0 = __ldg(&g_col[j]);
        int u1 = __ldg(&g_col[j + 1]);
        if (NV == 1) {
            uint2 p0 = *(const uint2*)(gbase + (size_t)u0 * 32);
            uint2 p1 = *(const uint2*)(gbase + (size_t)u1 * 32);
            a0 += blo(p0.x) + blo(p1.x); a1 += bhi(p0.x) + bhi(p1.x);
            a2 += blo(p0.y) + blo(p1.y); a3 += bhi(p0.y) + bhi(p1.y);
        } else {
            uint4 p0 = *(const uint4*)(gbase + (size_t)u0 * 32);
            uint4 p1 = *(const uint4*)(gbase + (size_t)u1 * 32);
            a0 += blo(p0.x) + blo(p1.x); a1 += bhi(p0.x) + bhi(p1.x);
            a2 += blo(p0.y) + blo(p1.y); a3 += bhi(p0.y) + bhi(p1.y);
            a4 += blo(p0.z) + blo(p1.z); a5 += bhi(p0.z) + bhi(p1.z);
            a6 += blo(p0.w) + blo(p1.w); a7 += bhi(p0.w) + bhi(p1.w);
        }
    }
    if (j < se.y) {
        int u = __ldg(&g_col[j]);
        if (NV == 1) {
            uint2 p = *(const uint2*)(gbase + (size_t)u * 32);
            a0 += blo(p.x); a1 += bhi(p.x);
            a2 += blo(p.y); a3 += bhi(p.y);
        } else {
            uint4 p = *(const uint4*)(gbase + (size_t)u * 32);
            a0 += blo(p.x); a1 += bhi(p.x);
            a2 += blo(p.y); a3 += bhi(p.y);
            a4 += blo(p.z); a5 += bhi(p.z);
            a6 += blo(p.w); a7 += bhi(p.w);
        }
    }

    float nv = g_norm[node];
    float o0 = nv * a0, o1 = nv * a1, o2 = nv * a2, o3 = nv * a3;
    if (NV == 1) {
        size_t eb = (size_t)node * 64 + q * 4;
        *(uint2*)&Hout[eb] = make_uint2(pack_bf16x2(o0, o1), pack_bf16x2(o2, o3));
        if (WS) {
            size_t wb = (size_t)node * 32 + q * 2;
            *(uint2*)&Hsout[wb] =
                make_uint2(pack_bf16x2(nv * o0, nv * o1), pack_bf16x2(nv * o2, nv * o3));
        }
    } else {
        float o4 = nv * a4, o5 = nv * a5, o6 = nv * a6, o7 = nv * a7;
        size_t eb = (size_t)node * 64 + q * 8;
        uint4 w;
        w.x = pack_bf16x2(o0, o1); w.y = pack_bf16x2(o2, o3);
        w.z = pack_bf16x2(o4, o5); w.w = pack_bf16x2(o6, o7);
        *(uint4*)&Hout[eb] = w;
        if (WS) {
            size_t wb = (size_t)node * 32 + q * 4;
            uint4 ws;
            ws.x = pack_bf16x2(nv * o0, nv * o1); ws.y = pack_bf16x2(nv * o2, nv * o3);
            ws.z = pack_bf16x2(nv * o4, nv * o5); ws.w = pack_bf16x2(nv * o6, nv * o7);
            *(uint4*)&Hsout[wb] = ws;
        }
    }
}

// ---------------- bf16 tensor-core GEMM + bias + ReLU (hi/lo quads) -------------
#define ASTR 20
#define BQSTR 12   // uint4 stride per n-column

__device__ __forceinline__ void mma_bf16(float* c, uint32_t a0, uint32_t a1,
                                         uint32_t a2, uint32_t a3,
                                         uint32_t b0, uint32_t b1) {
    asm volatile(
        "mma.sync.aligned.m16n8k16.row.col.f32.bf16.bf16.f32 "
        "{%0,%1,%2,%3}, {%4,%5,%6,%7}, {%8,%9}, {%0,%1,%2,%3};"
        : "+f"(c[0]), "+f"(c[1]), "+f"(c[2]), "+f"(c[3])
        : "r"(a0), "r"(a1), "r"(a2), "r"(a3), "r"(b0), "r"(b1));
}

template <bool WSC>
__global__ void __launch_bounds__(256) k_gemm_tc(
    const uint16_t* __restrict__ H0, const uint16_t* __restrict__ H1,
    const uint16_t* __restrict__ H2, const uint32_t* __restrict__ Wq,
    const float* __restrict__ bias,
    uint16_t* __restrict__ Out, uint32_t* __restrict__ OutS)
{
    __shared__ float sbias[64];
    __shared__ uint32_t As[128 * ASTR];
    __shared__ uint4 Bq[64 * BQSTR];

    int tid = threadIdx.x;
    int warp = tid >> 5, lane = tid & 31;
    int lg = lane >> 2, lm = lane & 3;
    int row0 = blockIdx.x * 128;
    if (tid < 64) sbias[tid] = bias[tid];

    float acc[8][4];
#pragma unroll
    for (int nt = 0; nt < 8; nt++)
#pragma unroll
        for (int jj = 0; jj < 4; jj++) acc[nt][jj] = 0.f;

    const uint16_t* bufs[3] = {H0, H1, H2};
    const uint4* Wq4 = (const uint4*)Wq;

    for (int c = 0; c < 6; c++) {
        __syncthreads();
        {
            const uint16_t* H = bufs[c >> 1];
            int half = (c & 1) * 32;
#pragma unroll
            for (int it = 0; it < 2; it++) {
                int idx = tid + it * 256;
                int r = idx >> 2, q = idx & 3;
                uint4 w = *(const uint4*)&H[(size_t)(row0 + r) * 64 + half + q * 8];
                *(uint4*)&As[r * ASTR + q * 4] = w;
            }
        }
        {
            // 512 quads per chunk
#pragma unroll
            for (int it = 0; it < 2; it++) {
                int idx = tid + it * 256;
                int n = idx >> 3, P = idx & 7;
                Bq[n * BQSTR + P] = Wq4[(n * 6 + c) * 8 + P];
            }
        }
        __syncthreads();

        int rA = warp * 16 + lg;
#pragma unroll
        for (int ks = 0; ks < 2; ks++) {
            int kb = ks * 8 + lm;
            uint32_t a0 = As[rA * ASTR + kb];
            uint32_t a1 = As[(rA + 8) * ASTR + kb];
            uint32_t a2 = As[rA * ASTR + kb + 4];
            uint32_t a3 = As[(rA + 8) * ASTR + kb + 4];
            int bp = ks * 4 + lm;
#pragma unroll
            for (int nt = 0; nt < 8; nt++) {
                int col = nt * 8 + lg;
                uint4 bq = Bq[col * BQSTR + bp];
                mma_bf16(acc[nt], a0, a1, a2, a3, bq.x, bq.y);
                mma_bf16(acc[nt], a0, a1, a2, a3, bq.z, bq.w);
            }
        }
    }

    int r = row0 + warp * 16 + lg;
    float nv0 = 1.f, nv1 = 1.f;
    if (WSC) { nv0 = g_norm[r]; nv1 = g_norm[r + 8]; }
    int cb = lm * 2;
#pragma unroll
    for (int nt = 0; nt < 8; nt++) {
        int col = nt * 8 + cb;
        float b0 = sbias[col], b1 = sbias[col + 1];
        float v00 = fmaxf(acc[nt][0] + b0, 0.f);
        float v01 = fmaxf(acc[nt][1] + b1, 0.f);
        float v10 = fmaxf(acc[nt][2] + b0, 0.f);
        float v11 = fmaxf(acc[nt][3] + b1, 0.f);
        *(uint32_t*)&Out[(size_t)r * 64 + col] = pack_bf16x2(v00, v01);
        *(uint32_t*)&Out[(size_t)(r + 8) * 64 + col] = pack_bf16x2(v10, v11);
        if (WSC) {
            OutS[(size_t)r * 32 + (col >> 1)] = pack_bf16x2(nv0 * v00, nv0 * v01);
            OutS[(size_t)(r + 8) * 32 + (col >> 1)] = pack_bf16x2(nv1 * v10, nv1 * v11);
        }
    }
}

// ---------------- per-graph attention pooling (bf16 plane input) ----------------
__global__ void k_pool(const uint16_t* __restrict__ H, const float* __restrict__ Wg,
                       const float* __restrict__ bg, float* __restrict__ out) {
    int g = blockIdx.x;
    __shared__ float sWg[64];
    __shared__ float sgate[NPG];
    __shared__ float red[256];
    int t = threadIdx.x;
    if (t < 64) sWg[t] = Wg[t];
    __syncthreads();

    int lane = t & 31, w = t >> 5;
    float bgv = bg[0];
    for (int n = w; n < NPG; n += 8) {
        const uint16_t* hp = H + (size_t)(g * NPG + n) * LD;
        float v = b2f(hp[lane]) * sWg[lane] + b2f(hp[lane + 32]) * sWg[lane + 32];
#pragma unroll
        for (int o = 16; o; o >>= 1) v += __shfl_xor_sync(0xffffffffu, v, o);
        if (lane == 0) sgate[n] = v + bgv;
    }
    __syncthreads();

    float m = -INFINITY;
    for (int n = t; n < NPG; n += 256) m = fmaxf(m, sgate[n]);
    red[t] = m;
    __syncthreads();
    for (int s = 128; s; s >>= 1) { if (t < s) red[t] = fmaxf(red[t], red[t + s]); __syncthreads(); }
    float gmax = red[0];
    __syncthreads();

    float ssum = 0.f;
    for (int n = t; n < NPG; n += 256) {
        float e = expf(sgate[n] - gmax);
        sgate[n] = e;
        ssum += e;
    }
    red[t] = ssum;
    __syncthreads();
    for (int s = 128; s; s >>= 1) { if (t < s) red[t] += red[t + s]; __syncthreads(); }
    float z = red[0];
    __syncthreads();

    int d = t & 63, p = t >> 6;
    float acc = 0.f;
    for (int n = p; n < NPG; n += 4)
        acc += sgate[n] * b2f(H[(size_t)(g * NPG + n) * LD + d]);
    red[t] = acc;
    __syncthreads();
    if (t < 64)
        out[g * 64 + t] = (red[t] + red[t + 64] + red[t + 128] + red[t + 192]) / z;
}

// ---------------- launch ----------------
extern "C" void kernel_launch(void* const* d_in, const int* in_sizes, int n_in,
                              void* d_out, int out_size) {
    const float* x   = (const float*)d_in[0];
    const int*   src = (const int*)d_in[1];
    const int*   dst = (const int*)d_in[2];
    const float* W0 = (const float*)d_in[4];
    const float* b0 = (const float*)d_in[5];
    const float* W1 = (const float*)d_in[6];
    const float* b1 = (const float*)d_in[7];
    const float* W2 = (const float*)d_in[8];
    const float* b2 = (const float*)d_in[9];
    const float* W3 = (const float*)d_in[10];
    const float* b3 = (const float*)d_in[11];
    const float* Wg = (const float*)d_in[12];
    const float* bg = (const float*)d_in[13];
    float* out = (float*)d_out;

    uint16_t *M0, *P0, *P1, *T1, *T2;
    uint32_t *M0s, *P0s, *P1s, *T1s, *Wq;
    cudaGetSymbolAddress((void**)&M0, g_M0);
    cudaGetSymbolAddress((void**)&P0, g_P0);
    cudaGetSymbolAddress((void**)&P1, g_P1);
    cudaGetSymbolAddress((void**)&T1, g_T1);
    cudaGetSymbolAddress((void**)&T2, g_T2);
    cudaGetSymbolAddress((void**)&M0s, g_M0s);
    cudaGetSymbolAddress((void**)&P0s, g_P0s);
    cudaGetSymbolAddress((void**)&P1s, g_P1s);
    cudaGetSymbolAddress((void**)&T1s, g_T1s);
    cudaGetSymbolAddress((void**)&Wq, g_Wq);

    k_fused<<<DEG_NB + WPREP_NB, 256>>>(dst, W0, W1, W2, W3);        // #0
    k_base<<<(NN + 255) / 256, 256>>>();                             // #1
    k_fillpad<<<FILL_NB + PAD_NB, 256>>>(src, dst, x);               // #2

    const int sgrid = NN / 32;    // 5000
    const int ggrid = NN / 128;   // 1250

    // per-layer weight stride: 64*6*8 quads * 4 words = 12288 words
    // ---- layer 0 ----  (#3 = first spmm — ncu target)
    k_spmm<1, true><<<sgrid, 256>>>(M0s, T1, T1s);
    k_spmm<1, false><<<sgrid, 256>>>(T1s, T2, nullptr);
    k_gemm_tc<true><<<ggrid, 256>>>(M0, T1, T2, Wq + 0 * 12288, b0, P0, P0s);

    // ---- layer 1 ----
    k_spmm<2, true><<<sgrid, 256>>>(P0s, T1, T1s);
    k_spmm<2, false><<<sgrid, 256>>>(T1s, T2, nullptr);
    k_gemm_tc<true><<<ggrid, 256>>>(P0, T1, T2, Wq + 1 * 12288, b1, P1, P1s);

    // ---- layer 2 ----
    k_spmm<2, true><<<sgrid, 256>>>(P1s, T1, T1s);
    k_spmm<2, false><<<sgrid, 256>>>(T1s, T2, nullptr);
    k_gemm_tc<true><<<ggrid, 256>>>(P1, T1, T2, Wq + 2 * 12288, b2, P0, P0s);

    // ---- layer 3 ----
    k_spmm<2, true><<<sgrid, 256>>>(P0s, T1, T1s);
    k_spmm<2, false><<<sgrid, 256>>>(T1s, T2, nullptr);
    k_gemm_tc<false><<<ggrid, 256>>>(P0, T1, T2, Wq + 3 * 12288, b3, P1, nullptr);

    // ---- pooling ----
    k_pool<<<GG, 256>>>(P1, Wg, bg, out);
}